// round 6
// baseline (speedup 1.0000x reference)
#include <cuda_runtime.h>
#include <math.h>

// ---------------------------------------------------------------------------
// CoDAConv2d rewritten (single kernel):
//   act_o  = sum_c x_c * (A_o^T nb)_c + nb.b_o
//   norm_o = sqrt(x^T G_o x + 2 u_o^T x + s_o) + eps
// Thread t=(o,c,s): 16 o x 8 c x 2 s = 256 threads. s splits the 4 packed
// channel pairs. Per-block prologue builds all tables from w_pred/b_pred in
// smem (no prep kernel). Warp-phase staggered pixel groups. f32x2 FMA core.
// ---------------------------------------------------------------------------

#define B_  4
#define CI  8
#define CO  16
#define HH  112
#define WW  112
#define PATCH 72

#define CHUNK 16
#define COLS  (CHUNK + 2)               // 18
#define TILE_ELEMS (3 * COLS * 8)       // 432
#define NCHUNK (WW / CHUNK)             // 7
#define NTASK  (B_ * HH * NCHUNK)       // 3136
#define NT 256
#define GRID   296                      // 148 SMs * 2 blocks

typedef unsigned long long ull;

__device__ int gCtr  = 0;
__device__ int gDone = 0;

// --- f32x2 helpers -----------------------------------------------------------
__device__ __forceinline__ ull ffma2(ull a, ull b, ull c) {
    ull d; asm("fma.rn.f32x2 %0, %1, %2, %3;" : "=l"(d) : "l"(a), "l"(b), "l"(c));
    return d;
}
__device__ __forceinline__ ull fadd2(ull a, ull b) {
    ull d; asm("add.rn.f32x2 %0, %1, %2;" : "=l"(d) : "l"(a), "l"(b));
    return d;
}
__device__ __forceinline__ ull pack2(float lo, float hi) {
    ull d; asm("mov.b64 %0, {%1, %2};" : "=l"(d) : "f"(lo), "f"(hi));
    return d;
}
__device__ __forceinline__ float hsum2(ull a) {
    float lo, hi; asm("mov.b64 {%0, %1}, %2;" : "=f"(lo), "=f"(hi) : "l"(a));
    return lo + hi;
}

// --- prefetch loader (256 threads, 2 regs each) -------------------------------
__device__ __forceinline__ void load_task(const float* __restrict__ in,
                                          int task, int t, float pre[2]) {
    const int rowid = task / NCHUNK;
    const int cw    = (task % NCHUNK) * CHUNK;
    const int b     = rowid / HH;
    const int h     = rowid % HH;
    #pragma unroll
    for (int k = 0; k < 2; k++) {
        int idx = t + k * NT;
        float v = 0.f;
        if (idx < TILE_ELEMS) {
            int ch   = idx & 7;
            int rest = idx >> 3;
            int col  = rest % COLS;
            int r    = rest / COLS;
            int ir   = h - 1 + r;
            int ic   = cw - 1 + col;
            if ((unsigned)ir < (unsigned)HH && (unsigned)ic < (unsigned)WW)
                v = __ldg(&in[((b * CI + ch) * HH + ir) * WW + ic]);
        }
        pre[k] = v;
    }
}

// --- single fused kernel -------------------------------------------------------
__global__ __launch_bounds__(NT, 2)
void coda_kernel(const float* __restrict__ in,
                 const float* __restrict__ w_pred,
                 const float* __restrict__ b_pred,
                 float* __restrict__ out) {
    const int t = threadIdx.x;
    const int c = t & 7;
    const int s = (t >> 3) & 1;
    const int o = t >> 4;

    __shared__ __align__(16) float sw[PATCH * 16 * 8];   // 36 KB, w_pred staged
    __shared__ __align__(16) float sb[PATCH * 16];       // 4.5 KB, b_pred staged
    __shared__ float tile[3][COLS][8];
    __shared__ int   sTask;

    // ---- stage predictor weights ----
    for (int i = t; i < PATCH * 16 * 8; i += NT) sw[i] = w_pred[i];
    for (int i = t; i < PATCH * 16; i += NT)     sb[i] = b_pred[i];
    __syncthreads();

    // ---- build per-thread constant tables ----
    // F pairs: this thread's 2 channel pairs (c' = 4s+2e, 4s+2e+1), taps j
    ull Fp[18];
    #pragma unroll
    for (int e = 0; e < 2; e++) {
        #pragma unroll
        for (int j = 0; j < 9; j++) {
            const int plo = (4 * s + 2 * e) * 9 + j;      // c'=4s+2e
            Fp[e * 9 + j] = pack2(sw[((plo)     * 16 + o) * 8 + c],
                                  sw[((plo + 9) * 16 + o) * 8 + c]); // c'+1 -> p+9
        }
    }
    // bias-conv taps (s=0 lanes only)
    float Zreg[9];
    #pragma unroll
    for (int j = 0; j < 9; j++)
        Zreg[j] = s ? 0.f : sb[(c * 9 + j) * 16 + o];

    // Gram row G[o][c][0..7], u, s  (split p over s, shfl-combine)
    float G8[8] = {0.f, 0.f, 0.f, 0.f, 0.f, 0.f, 0.f, 0.f};
    float uacc = 0.f, ssum = 0.f;
    {
        const int pbase = s * 36;
        #pragma unroll 4
        for (int pp = 0; pp < 36; pp++) {
            const int p = pbase + pp;
            const float* row = &sw[(p * 16 + o) * 8];
            const float wc = row[c];
            const float4 k0 = *(const float4*)row;
            const float4 k1 = *(const float4*)(row + 4);
            const float bv = sb[p * 16 + o];
            G8[0] = fmaf(wc, k0.x, G8[0]); G8[1] = fmaf(wc, k0.y, G8[1]);
            G8[2] = fmaf(wc, k0.z, G8[2]); G8[3] = fmaf(wc, k0.w, G8[3]);
            G8[4] = fmaf(wc, k1.x, G8[4]); G8[5] = fmaf(wc, k1.y, G8[5]);
            G8[6] = fmaf(wc, k1.z, G8[6]); G8[7] = fmaf(wc, k1.w, G8[7]);
            uacc = fmaf(wc, bv, uacc);
            ssum = fmaf(bv, bv, ssum);
        }
        #pragma unroll
        for (int i = 0; i < 8; i++)
            G8[i] += __shfl_xor_sync(0xffffffffu, G8[i], 8);
        uacc += __shfl_xor_sync(0xffffffffu, uacc, 8);
        ssum += __shfl_xor_sync(0xffffffffu, ssum, 8);
    }
    ull Qp[2];
    Qp[0] = pack2(s ? G8[4] : G8[0], s ? G8[5] : G8[1]);
    Qp[1] = pack2(s ? G8[6] : G8[2], s ? G8[7] : G8[3]);
    const ull   qinit = s ? 0ull : pack2(2.f * uacc, 0.f);
    const float Qs    = ssum * (1.f / 16.f);    // s[o]/16, summed over 16 lanes

    const int wphase = (t >> 5) & 3;            // warp-id mod 4 (group stagger)

    // ---- persistent task loop ----
    float pre[2];
    if (t == 0) sTask = atomicAdd(&gCtr, 1);
    __syncthreads();
    int task = sTask;
    load_task(in, task, t, pre);

    while (true) {
        #pragma unroll
        for (int k = 0; k < 2; k++) {
            int idx = t + k * NT;
            if (idx < TILE_ELEMS) ((float*)tile)[idx] = pre[k];
        }
        if (t == 0) sTask = atomicAdd(&gCtr, 1);
        __syncthreads();
        const int nxt = sTask;
        if (nxt < NTASK) load_task(in, nxt, t, pre);

        const int rowid = task / NCHUNK;
        const int cw    = (task % NCHUNK) * CHUNK;
        const int b     = rowid / HH;
        const int h     = rowid % HH;
        float* orow = &out[((b * CO + o) * HH + h) * WW + cw];

        #pragma unroll 1
        for (int g = 0; g < 4; g++) {
            const int wlb = ((g + wphase) & 3) * 4;   // staggered group start

            ull  m0[4], m1[4];
            float z[4], xc[4];
            ull  qp[4];
            #pragma unroll
            for (int px = 0; px < 4; px++) { m0[px] = 0ull; m1[px] = 0ull; z[px] = 0.f; }

            #pragma unroll
            for (int dh = 0; dh < 3; dh++) {
                #pragma unroll
                for (int k = 0; k < 6; k++) {
                    const float* pv = &tile[dh][wlb + k][0];
                    const ulonglong2 V = ((const ulonglong2*)pv)[s];
                    const float vc = pv[c];

                    const int pxlo = (k - 2 > 0) ? (k - 2) : 0;
                    const int pxhi = (k < 3) ? k : 3;
                    #pragma unroll
                    for (int px = pxlo; px <= pxhi; px++) {
                        const int j = dh * 3 + (k - px);
                        m0[px] = ffma2(V.x, Fp[0 + j], m0[px]);
                        m1[px] = ffma2(V.y, Fp[9 + j], m1[px]);
                        z[px]  = fmaf(vc, Zreg[j], z[px]);   // Zreg=0 on s=1
                    }
                    if (dh == 1 && k >= 1 && k <= 4) {
                        const int px = k - 1;
                        xc[px] = vc;
                        qp[px] = fadd2(ffma2(V.x, Qp[0], qinit),
                                       ffma2(V.y, Qp[1], 0ull));
                    }
                }
            }

            // per-pixel scalars: r[0..3]=av partial, r[4..7]=qv partial
            float r[8];
            #pragma unroll
            for (int px = 0; px < 4; px++) {
                float m = hsum2(fadd2(m0[px], m1[px]));
                r[px]     = fmaf(xc[px], m, z[px]);
                r[px + 4] = fmaf(xc[px], hsum2(qp[px]), Qs);
            }

            // 8-value butterfly over lane bits 0..2 (c), then bit 3 (s)
            const bool h0 = c & 1, h1 = c & 2, h2 = c & 4;
            float s4[4];
            #pragma unroll
            for (int i = 0; i < 4; i++) {
                float give = h0 ? r[2 * i] : r[2 * i + 1];
                float got  = __shfl_xor_sync(0xffffffffu, give, 1);
                s4[i] = (h0 ? r[2 * i + 1] : r[2 * i]) + got;
            }
            float u2[2];
            #pragma unroll
            for (int i = 0; i < 2; i++) {
                float give = h1 ? s4[2 * i] : s4[2 * i + 1];
                float got  = __shfl_xor_sync(0xffffffffu, give, 2);
                u2[i] = (h1 ? s4[2 * i + 1] : s4[2 * i]) + got;
            }
            {
                float give = h2 ? u2[0] : u2[1];
                float got  = __shfl_xor_sync(0xffffffffu, give, 4);
                float tot  = (h2 ? u2[1] : u2[0]) + got;      // half-sum of r[c]
                tot += __shfl_xor_sync(0xffffffffu, tot, 8);  // add other s-half
                float other = __shfl_xor_sync(0xffffffffu, tot, 4);
                if (c < 4 && s == 0) {
                    // reference denom = sqrt(qv)+1e-6; qv bounded away from 0,
                    // so av * rsqrt(qv) is within ~1e-5 relative of it.
                    float qv = fmaxf(other, 1e-20f);
                    orow[wlb + c] = tot * rsqrtf(qv);
                }
            }
        }

        __syncthreads();
        if (nxt >= NTASK) break;
        task = nxt;
    }

    // ---- counter reset for next graph replay: last block out resets ----
    if (t == 0) {
        int old = atomicAdd(&gDone, 1);
        if (old == (int)gridDim.x - 1) {
            atomicExch(&gCtr, 0);
            atomicExch(&gDone, 0);
        }
    }
}

// ---------------------------------------------------------------------------
extern "C" void kernel_launch(void* const* d_in, const int* in_sizes, int n_in,
                              void* d_out, int out_size) {
    const float* in_tensor = (const float*)d_in[0];
    const float* w_pred    = (const float*)d_in[1];
    const float* b_pred    = (const float*)d_in[2];
    float* out = (float*)d_out;

    coda_kernel<<<GRID, NT>>>(in_tensor, w_pred, b_pred, out);
}

// round 8
// speedup vs baseline: 1.1365x; 1.1365x over previous
#include <cuda_runtime.h>
#include <math.h>

// ---------------------------------------------------------------------------
// CoDAConv2d rewritten (single fused kernel):
//   act_o  = sum_c x_c * (A_o^T nb)_c + nb.b_o
//   norm_o = sqrt(x^T G_o x + 2 u_o^T x + s_o) + eps
// Thread t=(o,c). f32x2 packed FMA over channel pairs; 4px register blocking;
// 8-value/8-lane butterfly reduction; rsqrt epilogue; atomic task scheduler.
// Prep (table build) runs on block 0 only; other blocks spin on a flag
// (all 444 blocks are resident at occupancy 3 -> spin is deadlock-free).
// ---------------------------------------------------------------------------

#define B_  4
#define CI  8
#define CO  16
#define HH  112
#define WW  112
#define PATCH 72

#define CHUNK 16
#define COLS  (CHUNK + 2)               // 18
#define TILE_ELEMS (3 * COLS * 8)       // 432
#define NCHUNK (WW / CHUNK)             // 7
#define NTASK  (B_ * HH * NCHUNK)       // 3136
#define GRID   444                      // 148 SMs * 3 blocks (all resident)

typedef unsigned long long ull;

// packed-pair tables (index t = o*8+c)
__device__ ull   gF2[36 * 128];   // [i*9+j][t] : (F[c'=2i], F[c'=2i+1]) at tap j
__device__ float gZ[9 * 128];     // bias-conv taps
__device__ ull   gQ2[4 * 128];    // (G[c][2k],G[c][2k+1])
__device__ float gU[128];         // 2*u[o][c]
__device__ float gS[128];         // s[o]/8
__device__ int   gCtr  = 0;
__device__ int   gDone = 0;
__device__ int   gFlag = 0;

// --- f32x2 helpers -----------------------------------------------------------
__device__ __forceinline__ ull ffma2(ull a, ull b, ull c) {
    ull d; asm("fma.rn.f32x2 %0, %1, %2, %3;" : "=l"(d) : "l"(a), "l"(b), "l"(c));
    return d;
}
__device__ __forceinline__ ull fadd2(ull a, ull b) {
    ull d; asm("add.rn.f32x2 %0, %1, %2;" : "=l"(d) : "l"(a), "l"(b));
    return d;
}
__device__ __forceinline__ ull pack2(float lo, float hi) {
    ull d; asm("mov.b64 %0, {%1, %2};" : "=l"(d) : "f"(lo), "f"(hi));
    return d;
}
__device__ __forceinline__ float hsum2(ull a) {
    float lo, hi; asm("mov.b64 {%0, %1}, %2;" : "=f"(lo), "=f"(hi) : "l"(a));
    return lo + hi;
}

// --- prefetch loader --------------------------------------------------------
__device__ __forceinline__ void load_task(const float* __restrict__ in,
                                          int task, int t, float pre[4]) {
    const int rowid = task / NCHUNK;
    const int cw    = (task % NCHUNK) * CHUNK;
    const int b     = rowid / HH;
    const int h     = rowid % HH;
    #pragma unroll
    for (int k = 0; k < 4; k++) {
        int idx = t + k * 128;
        float v = 0.f;
        if (idx < TILE_ELEMS) {
            int ch   = idx & 7;
            int rest = idx >> 3;
            int col  = rest % COLS;
            int r    = rest / COLS;
            int ir   = h - 1 + r;
            int ic   = cw - 1 + col;
            if ((unsigned)ir < (unsigned)HH && (unsigned)ic < (unsigned)WW)
                v = __ldg(&in[((b * CI + ch) * HH + ir) * WW + ic]);
        }
        pre[k] = v;
    }
}

// --- main kernel ----------------------------------------------------------------
__global__ __launch_bounds__(128, 3)
void coda_main_kernel(const float* __restrict__ in,
                      const float* __restrict__ w_pred,
                      const float* __restrict__ b_pred,
                      float* __restrict__ out) {
    const int t = threadIdx.x;
    const int o = t >> 3;
    const int c = t & 7;

    // ===== fused prep: block 0 builds tables; everyone else waits ==========
    if (blockIdx.x == 0) {
        // F / Z tables (each thread owns column t)
        #pragma unroll 4
        for (int bx = 0; bx < 36; bx++) {
            const int i = bx / 9, j = bx % 9;
            float lo = w_pred[(((2 * i)     * 9 + j) * 16 + o) * 8 + c];
            float hi = w_pred[(((2 * i + 1) * 9 + j) * 16 + o) * 8 + c];
            gF2[bx * 128 + t] = pack2(lo, hi);
            if (bx < 9) gZ[bx * 128 + t] = b_pred[(c * 9 + bx) * 16 + o];
        }
        // Gram row G[o][c][0..7], u, s
        float G8[8] = {0.f, 0.f, 0.f, 0.f, 0.f, 0.f, 0.f, 0.f};
        float uacc = 0.f, ssum = 0.f;
        #pragma unroll 4
        for (int p = 0; p < PATCH; p++) {
            const float wc = w_pred[(p * 16 + o) * 8 + c];
            const float4 k0 = *(const float4*)&w_pred[(p * 16 + o) * 8];
            const float4 k1 = *(const float4*)&w_pred[(p * 16 + o) * 8 + 4];
            const float bv = b_pred[p * 16 + o];
            G8[0] = fmaf(wc, k0.x, G8[0]); G8[1] = fmaf(wc, k0.y, G8[1]);
            G8[2] = fmaf(wc, k0.z, G8[2]); G8[3] = fmaf(wc, k0.w, G8[3]);
            G8[4] = fmaf(wc, k1.x, G8[4]); G8[5] = fmaf(wc, k1.y, G8[5]);
            G8[6] = fmaf(wc, k1.z, G8[6]); G8[7] = fmaf(wc, k1.w, G8[7]);
            uacc = fmaf(wc, bv, uacc);
            ssum = fmaf(bv, bv, ssum);
        }
        #pragma unroll
        for (int kk = 0; kk < 4; kk++)
            gQ2[kk * 128 + t] = pack2(G8[2 * kk], G8[2 * kk + 1]);
        gU[t] = 2.0f * uacc;
        gS[t] = ssum * 0.125f;

        __threadfence();
        __syncthreads();
        if (t == 0) atomicExch(&gFlag, 1);   // release
    } else {
        if (t == 0) {
            while (atomicAdd(&gFlag, 0) == 0) __nanosleep(64);
        }
        __syncthreads();
        __threadfence();                      // acquire
    }

    // ===== per-thread constant tables (from globals) =========================
    ull Fp[36];
    #pragma unroll
    for (int p = 0; p < 36; p++) Fp[p] = gF2[p * 128 + t];
    float Zreg[9];
    #pragma unroll
    for (int j = 0; j < 9; j++) Zreg[j] = gZ[j * 128 + t];
    ull Qp[4];
    #pragma unroll
    for (int k = 0; k < 4; k++) Qp[k] = gQ2[k * 128 + t];
    const ull   qinit = pack2(gU[t], 0.f);
    const float Qs    = gS[t];

    __shared__ float tile[3][COLS][8];
    __shared__ int   sTask;

    float pre[4];

    if (t == 0) sTask = atomicAdd(&gCtr, 1);
    __syncthreads();
    int task = sTask;
    if (task < NTASK) {
        load_task(in, task, t, pre);

        while (true) {
            #pragma unroll
            for (int k = 0; k < 4; k++) {
                int idx = t + k * 128;
                if (idx < TILE_ELEMS) ((float*)tile)[idx] = pre[k];
            }
            if (t == 0) sTask = atomicAdd(&gCtr, 1);
            __syncthreads();
            const int nxt = sTask;
            if (nxt < NTASK) load_task(in, nxt, t, pre);

            const int rowid = task / NCHUNK;
            const int cw    = (task % NCHUNK) * CHUNK;
            const int b     = rowid / HH;
            const int h     = rowid % HH;
            float* orow = &out[((b * CO + o) * HH + h) * WW + cw];

            #pragma unroll 1
            for (int wlb = 0; wlb < CHUNK; wlb += 4) {
                ull  m0[4], m1[4], m2[4], m3[4];
                float z[4], xc[4];
                ull  qp[4];
                #pragma unroll
                for (int px = 0; px < 4; px++) {
                    m0[px] = 0ull; m1[px] = 0ull; m2[px] = 0ull; m3[px] = 0ull;
                    z[px] = 0.f;
                }

                #pragma unroll
                for (int dh = 0; dh < 3; dh++) {
                    #pragma unroll
                    for (int k = 0; k < 6; k++) {
                        const float* pv = &tile[dh][wlb + k][0];
                        const ulonglong2 VA = *(const ulonglong2*)pv;
                        const ulonglong2 VB = *((const ulonglong2*)pv + 1);
                        const float vc = pv[c];

                        const int pxlo = (k - 2 > 0) ? (k - 2) : 0;
                        const int pxhi = (k < 3) ? k : 3;
                        #pragma unroll
                        for (int px = pxlo; px <= pxhi; px++) {
                            const int j = dh * 3 + (k - px);
                            m0[px] = ffma2(VA.x, Fp[ 0 + j], m0[px]);
                            m1[px] = ffma2(VA.y, Fp[ 9 + j], m1[px]);
                            m2[px] = ffma2(VB.x, Fp[18 + j], m2[px]);
                            m3[px] = ffma2(VB.y, Fp[27 + j], m3[px]);
                            z[px]  = fmaf(vc, Zreg[j], z[px]);
                        }
                        if (dh == 1 && k >= 1 && k <= 4) {
                            const int px = k - 1;
                            xc[px] = vc;
                            ull qa = ffma2(VA.x, Qp[0], qinit);
                            qa = ffma2(VB.x, Qp[2], qa);
                            ull qb = ffma2(VA.y, Qp[1], 0ull);
                            qb = ffma2(VB.y, Qp[3], qb);
                            qp[px] = fadd2(qa, qb);
                        }
                    }
                }

                // per-pixel scalars
                float r[8];
                #pragma unroll
                for (int px = 0; px < 4; px++) {
                    float m = hsum2(fadd2(fadd2(m0[px], m1[px]), fadd2(m2[px], m3[px])));
                    r[px]     = fmaf(xc[px], m, z[px]);            // av partial
                    r[px + 4] = fmaf(xc[px], hsum2(qp[px]), Qs);   // qv partial
                }

                // 8-value / 8-lane butterfly reduction
                const bool h0 = c & 1, h1 = c & 2, h2 = c & 4;
                float s4[4];
                #pragma unroll
                for (int i = 0; i < 4; i++) {
                    float give = h0 ? r[2 * i] : r[2 * i + 1];
                    float got  = __shfl_xor_sync(0xffffffffu, give, 1);
                    s4[i] = (h0 ? r[2 * i + 1] : r[2 * i]) + got;
                }
                float u2[2];
                #pragma unroll
                for (int i = 0; i < 2; i++) {
                    float give = h1 ? s4[2 * i] : s4[2 * i + 1];
                    float got  = __shfl_xor_sync(0xffffffffu, give, 2);
                    u2[i] = (h1 ? s4[2 * i + 1] : s4[2 * i]) + got;
                }
                {
                    float give = h2 ? u2[0] : u2[1];
                    float got  = __shfl_xor_sync(0xffffffffu, give, 4);
                    float tot  = (h2 ? u2[1] : u2[0]) + got;     // lane c: sum of r[c]
                    float other = __shfl_xor_sync(0xffffffffu, tot, 4);
                    if (c < 4) {
                        // reference denom = sqrt(qv)+1e-6; qv bounded away from 0,
                        // so av * rsqrt(qv) is within ~1e-5 relative of it.
                        float qv = fmaxf(other, 1e-20f);
                        orow[wlb + c] = tot * rsqrtf(qv);
                    }
                }
            }

            __syncthreads();
            if (nxt >= NTASK) break;
            task = nxt;
        }
    }

    // ---- reset for next graph replay: last block out resets everything ----
    if (t == 0) {
        int old = atomicAdd(&gDone, 1);
        if (old == (int)gridDim.x - 1) {
            atomicExch(&gCtr, 0);
            atomicExch(&gFlag, 0);
            atomicExch(&gDone, 0);
        }
    }
}

// ---------------------------------------------------------------------------
extern "C" void kernel_launch(void* const* d_in, const int* in_sizes, int n_in,
                              void* d_out, int out_size) {
    const float* in_tensor = (const float*)d_in[0];
    const float* w_pred    = (const float*)d_in[1];
    const float* b_pred    = (const float*)d_in[2];
    float* out = (float*)d_out;

    coda_main_kernel<<<GRID, 128>>>(in_tensor, w_pred, b_pred, out);
}